// round 12
// baseline (speedup 1.0000x reference)
#include <cuda_runtime.h>
#include <cstdint>

// x: [8192, 4096] fp32 row-major. loss = N*sum(x*x) - sum_d(colsum_d)^2
#define N_ROWS   8192
#define D_COLS   4096
#define ROW_F4   (D_COLS / 4)               // 1024 float4 per row

#define CBLK     4                          // column groups, 1024 cols (4KB seg/row)
#define RCHUNKS  128                        // row chunks of 64 rows
#define ROWS_PER_CHUNK (N_ROWS / RCHUNKS)   // 64
#define NBLOCKS  (CBLK * RCHUNKS)           // 512
#define NTHREADS 256

// Dual-path split: TMA streams rows [0,48), LDG streams rows [48,64)
#define TMA_ROWS    48
#define LDG_ROWS    16
#define SEG_BYTES   4096                    // 1024 cols * 4B, contiguous per row
#define STAGE_ROWS  4
#define STAGE_BYTES (STAGE_ROWS * SEG_BYTES)       // 16 KB
#define NSTAGE      3                               // 48 KB dynamic smem
#define NITER       (TMA_ROWS / STAGE_ROWS)         // 12

// Deputy-chain tail (proven since R8)
#define SUPER    16
#define NSUPER   (RCHUNKS / SUPER)          // 8

// Scratch (__device__ globals; no allocations allowed)
__device__ float    g_part [RCHUNKS * D_COLS];        // 2 MB level-1 colsum partials
__device__ float    g_part2[CBLK * NSUPER * 1024];    // 128 KB level-2
__device__ float    g_ss_part[NBLOCKS];
__device__ float    g_colsq[CBLK];
__device__ unsigned g_cnt_super[CBLK * NSUPER];
__device__ unsigned g_cnt_cg[CBLK];
__device__ unsigned g_cnt_final;

// ---------------- PTX helpers ----------------
__device__ __forceinline__ uint32_t smem_u32(const void* p) {
    return (uint32_t)__cvta_generic_to_shared(p);
}
__device__ __forceinline__ void mbar_init(uint32_t a, uint32_t cnt) {
    asm volatile("mbarrier.init.shared.b64 [%0], %1;" :: "r"(a), "r"(cnt) : "memory");
}
__device__ __forceinline__ void mbar_arrive(uint32_t a) {
    asm volatile("mbarrier.arrive.shared.b64 _, [%0];" :: "r"(a) : "memory");
}
__device__ __forceinline__ void mbar_expect_tx(uint32_t a, uint32_t bytes) {
    asm volatile("mbarrier.arrive.expect_tx.shared.b64 _, [%0], %1;"
                 :: "r"(a), "r"(bytes) : "memory");
}
__device__ __forceinline__ void bulk_g2s(uint32_t dst, const void* src,
                                         uint32_t bytes, uint32_t mbar) {
    asm volatile("cp.async.bulk.shared::cta.global.mbarrier::complete_tx::bytes "
                 "[%0], [%1], %2, [%3];"
                 :: "r"(dst), "l"(src), "r"(bytes), "r"(mbar) : "memory");
}
__device__ __forceinline__ void mbar_wait(uint32_t mbar, uint32_t parity) {
    asm volatile(
        "{\n\t.reg .pred P;\n\t"
        "W_%=: mbarrier.try_wait.parity.acquire.cta.shared::cta.b64 P, [%0], %1, 0x989680;\n\t"
        "@P bra D_%=;\n\t"
        "bra W_%=;\n\t"
        "D_%=:\n\t}"
        :: "r"(mbar), "r"(parity) : "memory");
}
__device__ __forceinline__ void fence_proxy_async_s() {
    asm volatile("fence.proxy.async.shared::cta;" ::: "memory");
}

// block-reduce one float over 256 threads -> valid in thread 0
__device__ __forceinline__ float block_sum(float v, float* sh8, int t) {
    #pragma unroll
    for (int o = 16; o > 0; o >>= 1) v += __shfl_down_sync(0xffffffffu, v, o);
    if ((t & 31) == 0) sh8[t >> 5] = v;
    __syncthreads();
    float r = 0.f;
    if (t < 8) {
        r = sh8[t];
        #pragma unroll
        for (int o = 4; o > 0; o >>= 1) r += __shfl_down_sync(0xffu, r, o);
    }
    __syncthreads();
    return r;
}

extern __shared__ char smem_dyn[];   // NSTAGE * 16 KB stage buffers

__global__ __launch_bounds__(NTHREADS)
void stability_loss_kernel(const float* __restrict__ x, float* __restrict__ out)
{
    __shared__ alignas(16) uint64_t mb_full[NSTAGE];
    __shared__ alignas(16) uint64_t mb_empty[NSTAGE];
    __shared__ float    sh_red[8];
    __shared__ unsigned sh_old;

    const int t     = threadIdx.x;
    const int cg    = blockIdx.x;            // 0..3
    const int chunk = blockIdx.y;            // 0..127
    const int sg    = chunk >> 4;

    const uint32_t fb0  = smem_u32(&mb_full[0]);
    const uint32_t eb0  = smem_u32(&mb_empty[0]);
    const uint32_t stg0 = smem_u32(&smem_dyn[0]);

    // gmem base: rows [chunk*64, +64), cols [cg*1024, +1024)
    const char* gbase = (const char*)x +
        ((size_t)chunk * ROWS_PER_CHUNK * D_COLS + (size_t)cg * 1024) * 4;
    const size_t row_pitch = (size_t)D_COLS * 4;   // 16 KB

    if (t == 0) {
        #pragma unroll
        for (int s = 0; s < NSTAGE; ++s) {
            mbar_init(fb0 + 8 * s, 1);          // full: one expect_tx producer
            mbar_init(eb0 + 8 * s, NTHREADS);   // empty: all consumers arrive
        }
    }
    __syncthreads();

    // prologue: fill all 3 TMA stages (rows 0..11)
    if (t == 0) {
        #pragma unroll
        for (int i = 0; i < NSTAGE; ++i) {
            uint32_t mba = fb0 + 8 * i;
            uint32_t dst = stg0 + i * STAGE_BYTES;
            const char* src = gbase + (size_t)i * STAGE_ROWS * row_pitch;
            mbar_expect_tx(mba, STAGE_BYTES);
            #pragma unroll
            for (int j = 0; j < STAGE_ROWS; ++j)
                bulk_g2s(dst + j * SEG_BYTES, src + (size_t)j * row_pitch,
                         SEG_BYTES, mba);
        }
    }

    float4 cs = make_float4(0.f, 0.f, 0.f, 0.f);
    float  ss = 0.f;

    // ---------------- LDG path: rows [48,64) straight into registers ----------------
    // Issued before ring consumption so LSU-path loads overlap TMA-path transfers.
    {
        const float4* __restrict__ p = reinterpret_cast<const float4*>(
            gbase + (size_t)TMA_ROWS * row_pitch) + t;
        #pragma unroll 8
        for (int r = 0; r < LDG_ROWS; ++r) {
            float4 v = p[(size_t)r * ROW_F4];
            cs.x += v.x; cs.y += v.y; cs.z += v.z; cs.w += v.w;
            ss   += v.x*v.x + v.y*v.y + v.z*v.z + v.w*v.w;
        }
    }

    // ---------------- TMA ring: rows [0,48), producer-consumer ----------------
    int slot = 0, fphase = 0, ephase = 0;
    for (int i = 0; i < NITER; ++i) {
        mbar_wait(fb0 + 8 * slot, fphase);

        const float4* sv = reinterpret_cast<const float4*>(
            smem_dyn + slot * STAGE_BYTES);
        #pragma unroll
        for (int r = 0; r < STAGE_ROWS; ++r) {
            float4 v = sv[r * 256 + t];
            cs.x += v.x; cs.y += v.y; cs.z += v.z; cs.w += v.w;
            ss   += v.x*v.x + v.y*v.y + v.z*v.z + v.w*v.w;
        }

        mbar_arrive(eb0 + 8 * slot);   // non-blocking consume signal

        if (t == 0 && i + NSTAGE < NITER) {
            mbar_wait(eb0 + 8 * slot, ephase);   // all consumed -> refill
            const int ni = i + NSTAGE;
            uint32_t mba = fb0 + 8 * slot;
            uint32_t dst = stg0 + slot * STAGE_BYTES;
            const char* src = gbase + (size_t)ni * STAGE_ROWS * row_pitch;
            fence_proxy_async_s();
            mbar_expect_tx(mba, STAGE_BYTES);
            #pragma unroll
            for (int j = 0; j < STAGE_ROWS; ++j)
                bulk_g2s(dst + j * SEG_BYTES, src + (size_t)j * row_pitch,
                         SEG_BYTES, mba);
        }

        if (++slot == NSTAGE) { slot = 0; fphase ^= 1; ephase ^= 1; }
    }
    __syncthreads();   // re-converge before tail

    // write colsum partial (thread t owns f4-col cg*256+t of this chunk)
    reinterpret_cast<float4*>(g_part)[(size_t)chunk * ROW_F4 + cg * 256 + t] = cs;

    {
        float tot = block_sum(ss, sh_red, t);
        if (t == 0) g_ss_part[chunk * CBLK + cg] = tot;
    }

    // ---------------- Level 1 -> 2: last arrival of (cg,sg)'s 16 chunks ----------------
    __threadfence();
    if (t == 0) sh_old = atomicAdd(&g_cnt_super[cg * NSUPER + sg], 1u);
    __syncthreads();
    if (sh_old != SUPER - 1) return;
    if (t == 0) g_cnt_super[cg * NSUPER + sg] = 0;   // reset for next replay

    {
        const float4* P = reinterpret_cast<const float4*>(g_part);
        float4 s = make_float4(0.f, 0.f, 0.f, 0.f);
        #pragma unroll 4
        for (int c = 0; c < SUPER; ++c) {
            float4 v = __ldcg(&P[(size_t)(sg * SUPER + c) * ROW_F4 + cg * 256 + t]);
            s.x += v.x; s.y += v.y; s.z += v.z; s.w += v.w;
        }
        reinterpret_cast<float4*>(g_part2)[(size_t)(cg * NSUPER + sg) * 256 + t] = s;
    }

    // ---------------- Level 2 -> colsq: last super-deputy of this cg ----------------
    __threadfence();
    __syncthreads();
    if (t == 0) sh_old = atomicAdd(&g_cnt_cg[cg], 1u);
    __syncthreads();
    if (sh_old != NSUPER - 1) return;
    if (t == 0) g_cnt_cg[cg] = 0;

    {
        const float4* P2 = reinterpret_cast<const float4*>(g_part2);
        float4 s = make_float4(0.f, 0.f, 0.f, 0.f);
        #pragma unroll
        for (int sgi = 0; sgi < NSUPER; ++sgi) {
            float4 v = __ldcg(&P2[(size_t)(cg * NSUPER + sgi) * 256 + t]);
            s.x += v.x; s.y += v.y; s.z += v.z; s.w += v.w;
        }
        float sq = s.x*s.x + s.y*s.y + s.z*s.z + s.w*s.w;
        float csq = block_sum(sq, sh_red, t);
        if (t == 0) g_colsq[cg] = csq;
    }

    // ---------------- Final: last cg-deputy folds everything ----------------
    __threadfence();
    __syncthreads();
    if (t == 0) sh_old = atomicAdd(&g_cnt_final, 1u);
    __syncthreads();
    if (sh_old != CBLK - 1) return;
    if (t == 0) g_cnt_final = 0;

    {
        float ss2 = __ldcg(&g_ss_part[t]) + __ldcg(&g_ss_part[t + 256]);
        float cq  = (t < CBLK) ? __ldcg(&g_colsq[t]) : 0.f;

        #pragma unroll
        for (int o = 16; o > 0; o >>= 1) {
            ss2 += __shfl_down_sync(0xffffffffu, ss2, o);
            cq  += __shfl_down_sync(0xffffffffu, cq,  o);
        }
        __shared__ float sh_a[8], sh_b[8];
        if ((t & 31) == 0) { sh_a[t >> 5] = ss2; sh_b[t >> 5] = cq; }
        __syncthreads();
        if (t < 8) {
            float a = sh_a[t], c2 = sh_b[t];
            #pragma unroll
            for (int o = 4; o > 0; o >>= 1) {
                a  += __shfl_down_sync(0xffu, a,  o);
                c2 += __shfl_down_sync(0xffu, c2, o);
            }
            if (t == 0)
                out[0] = (float)N_ROWS * a - c2;
        }
    }
}

extern "C" void kernel_launch(void* const* d_in, const int* in_sizes, int n_in,
                              void* d_out, int out_size)
{
    const float* x = (const float*)d_in[0];
    float* out = (float*)d_out;
    (void)in_sizes; (void)n_in; (void)out_size;

    cudaFuncSetAttribute(stability_loss_kernel,
                         cudaFuncAttributeMaxDynamicSharedMemorySize,
                         NSTAGE * STAGE_BYTES);

    dim3 grid(CBLK, RCHUNKS);
    stability_loss_kernel<<<grid, NTHREADS, NSTAGE * STAGE_BYTES>>>(x, out);
}